// round 2
// baseline (speedup 1.0000x reference)
#include <cuda_runtime.h>
#include <math.h>

#define TT 500
#define NN 21
#define NPAD 24
#define BB 64

// ---------------- device scratch (no allocations allowed) ----------------
__device__ __align__(16) float g_A[NN * NN];        // A[n][j]
__device__ __align__(16) float g_W1zr[256 * 128];   // [c][k]: c<128 -> lzw1 bottom, else lrw1 bottom
__device__ __align__(16) float g_W1h[128 * 128];    // lhw1 bottom [c][k]
__device__ __align__(16) float g_W2g[384 * 128];    // [c][k]: Mz|Mr|Mh  (M = W2 @ lw2_top)
__device__ __align__(16) float g_W2zr[256 * 128];   // lzw2/lrw2 bottom [c][k]
__device__ __align__(16) float g_W2h[128 * 128];    // lhw2 bottom [c][k]
__device__ __align__(16) float g_c1[6 * 128];       // uz,ur,uh,cz,cr,ch
__device__ __align__(16) float g_c2[3 * 128];       // dz,dr,dh

// ---------------- smem layout for the main kernel ----------------
struct SM {
  float Y[TT * NN];        // Y[t][n] = (A @ x_t)[n], all steps precomputed
  float AT[NN * NPAD];     // AT[j][n] = A[n][j]  (pad cols 21..23 = 0)
  float H1T[128 * NPAD];   // H1 transposed: [feature][node]
  float H2T[128 * NPAD];
  float XT[128 * NPAD];    // scratch: H*R, then AH1
  float ZT[128 * NPAD];    // Z gate scratch
  float GZR[256 * NPAD];   // layer-2 gcn z/r pre-activations
  float GH[128 * NPAD];    // layer-2 gcn h pre-activation
  float uz[128], ur[128], uh[128], cz[128], cr[128], ch[128];
  float dz[128], dr[128], dh[128];
  float clsw[128];
  float OSUM[256];         // per (col, node-group) output accumulator
  float red[8];
};

// ---------------- helpers ----------------
__device__ __forceinline__ float2 ffma2(float2 a, float2 b, float2 c) {
  float2 d;
  asm("fma.rn.f32x2 %0, %1, %2, %3;"
      : "=l"(reinterpret_cast<unsigned long long&>(d))
      : "l"(reinterpret_cast<unsigned long long&>(a)),
        "l"(reinterpret_cast<unsigned long long&>(b)),
        "l"(reinterpret_cast<unsigned long long&>(c)));
  return d;
}

__device__ __forceinline__ float sigmoidf_(float v) {
  return 1.0f / (1.0f + __expf(-v));
}

// acc[p] += X[k][2*(P0+p) .. +1] * w[k] over k=0..127.  X is smem [128][NPAD],
// w is a 512B row in global ([c][k] layout, streamed via LDG.128).
template <int P0, int PAIRS>
__device__ __forceinline__ void dotcols(const float* __restrict__ h,
                                        const float* __restrict__ w,
                                        float2* acc) {
#pragma unroll 2
  for (int k = 0; k < 128; k += 4) {
    float4 w4 = *reinterpret_cast<const float4*>(w + k);
    const float* wf = reinterpret_cast<const float*>(&w4);
#pragma unroll
    for (int kk = 0; kk < 4; kk++) {
      float wv = wf[kk];
      float2 ws = make_float2(wv, wv);
      const float2* h2 = reinterpret_cast<const float2*>(h + (k + kk) * NPAD);
#pragma unroll
      for (int p = 0; p < PAIRS; p++) acc[p] = ffma2(h2[P0 + p], ws, acc[p]);
    }
  }
}

// ---------------- prep kernels ----------------
__global__ void prep_A_kernel(const int* __restrict__ ei,
                              const float* __restrict__ ew, int E) {
  if (threadIdx.x != 0 || blockIdx.x != 0) return;
  float deg[NN], dinv[NN];
  for (int n = 0; n < NN; n++) deg[n] = 1.0f;  // self loop weight 1
  for (int e = 0; e < E; e++) deg[ei[E + e]] += ew[e];
  for (int n = 0; n < NN; n++) dinv[n] = (deg[n] > 0.f) ? rsqrtf(deg[n]) : 0.f;
  for (int i = 0; i < NN * NN; i++) g_A[i] = 0.f;
  for (int e = 0; e < E; e++) {
    int s = ei[e], d = ei[E + e];
    g_A[d * NN + s] += dinv[s] * ew[e] * dinv[d];
  }
  for (int n = 0; n < NN; n++) g_A[n * NN + n] += dinv[n] * dinv[n];
}

__global__ void prep_W_kernel(
    const float* Wz1, const float* bz1, const float* lzw1, const float* lzb1,
    const float* Wr1, const float* br1, const float* lrw1, const float* lrb1,
    const float* Wh1, const float* bh1, const float* lhw1, const float* lhb1,
    const float* Wz2, const float* bz2, const float* lzw2, const float* lzb2,
    const float* Wr2, const float* br2, const float* lrw2, const float* lrb2,
    const float* Wh2, const float* bh2, const float* lhw2, const float* lhb2) {
  int t0 = blockIdx.x * blockDim.x + threadIdx.x;
  int nt = gridDim.x * blockDim.x;
  // bottom-half repacks (concat rows 128..255 act on H)
  for (int i = t0; i < 256 * 128; i += nt) {
    int c = i >> 7, k = i & 127;
    g_W1zr[i] = (c < 128) ? lzw1[(128 + k) * 128 + c]
                          : lrw1[(128 + k) * 128 + (c - 128)];
    g_W2zr[i] = (c < 128) ? lzw2[(128 + k) * 128 + c]
                          : lrw2[(128 + k) * 128 + (c - 128)];
  }
  for (int i = t0; i < 128 * 128; i += nt) {
    int c = i >> 7, k = i & 127;
    g_W1h[i] = lhw1[(128 + k) * 128 + c];
    g_W2h[i] = lhw2[(128 + k) * 128 + c];
  }
  // M_g[k][c] = sum_m W_g2[k][m] * l_gw2[m][c]  (top half rows of lw)
  for (int i = t0; i < 384 * 128; i += nt) {
    int c = i >> 7, k = i & 127;
    const float *W, *lw;
    int cc = c;
    if (c < 128) { W = Wz2; lw = lzw2; }
    else if (c < 256) { W = Wr2; lw = lrw2; cc = c - 128; }
    else { W = Wh2; lw = lhw2; cc = c - 256; }
    float s = 0.f;
    for (int m = 0; m < 128; m++) s += W[k * 128 + m] * lw[m * 128 + cc];
    g_W2g[i] = s;
  }
  // layer-1 rank-1 vectors + fused biases, layer-2 fused biases
  for (int c = t0; c < 128; c += nt) {
    float uz = 0, ur = 0, uh = 0, cz = 0, cr = 0, ch = 0, dz = 0, dr = 0, dh = 0;
    for (int m = 0; m < 128; m++) {
      uz += Wz1[m] * lzw1[m * 128 + c];
      ur += Wr1[m] * lrw1[m * 128 + c];
      uh += Wh1[m] * lhw1[m * 128 + c];
      cz += bz1[m] * lzw1[m * 128 + c];
      cr += br1[m] * lrw1[m * 128 + c];
      ch += bh1[m] * lhw1[m * 128 + c];
      dz += bz2[m] * lzw2[m * 128 + c];
      dr += br2[m] * lrw2[m * 128 + c];
      dh += bh2[m] * lhw2[m * 128 + c];
    }
    g_c1[0 * 128 + c] = uz;
    g_c1[1 * 128 + c] = ur;
    g_c1[2 * 128 + c] = uh;
    g_c1[3 * 128 + c] = cz + lzb1[c];
    g_c1[4 * 128 + c] = cr + lrb1[c];
    g_c1[5 * 128 + c] = ch + lhb1[c];
    g_c2[0 * 128 + c] = dz + lzb2[c];
    g_c2[1 * 128 + c] = dr + lrb2[c];
    g_c2[2 * 128 + c] = dh + lhb2[c];
  }
}

// ---------------- main fused recurrence: one CTA per batch ----------------
__global__ void __launch_bounds__(256, 1)
tgcn_main(const float* __restrict__ x, const float* __restrict__ clsw,
          const float* __restrict__ clsb, float* __restrict__ out) {
  extern __shared__ __align__(16) unsigned char smraw[];
  SM* s = reinterpret_cast<SM*>(smraw);
  const int tid = threadIdx.x;
  const int b = blockIdx.x;

  // ---- init: consts, zero state ----
  for (int i = tid; i < 128; i += 256) {
    s->uz[i] = g_c1[i];
    s->ur[i] = g_c1[128 + i];
    s->uh[i] = g_c1[256 + i];
    s->cz[i] = g_c1[384 + i];
    s->cr[i] = g_c1[512 + i];
    s->ch[i] = g_c1[640 + i];
    s->dz[i] = g_c2[i];
    s->dr[i] = g_c2[128 + i];
    s->dh[i] = g_c2[256 + i];
    s->clsw[i] = clsw[i];
  }
  for (int i = tid; i < NN * NPAD; i += 256) s->AT[i] = 0.f;
  for (int i = tid; i < 128 * NPAD; i += 256) {
    s->H1T[i] = 0.f;
    s->H2T[i] = 0.f;
    s->XT[i] = 0.f;
  }
  if (tid < 256) s->OSUM[tid] = 0.f;
  __syncthreads();
  for (int i = tid; i < NN * NN; i += 256) {
    int n = i / NN, j = i - n * NN;
    s->AT[j * NPAD + n] = g_A[i];
  }
  __syncthreads();
  // ---- precompute Y[t][n] = sum_j A[n][j] * x[b][t][j] for all t ----
  const float* xb = x + (size_t)b * TT * NN;
  for (int i = tid; i < TT * NN; i += 256) {
    int t = i / NN, n = i - t * NN;
    float acc = 0.f;
#pragma unroll
    for (int j = 0; j < NN; j++) acc += s->AT[j * NPAD + n] * xb[t * NN + j];
    s->Y[i] = acc;
  }
  __syncthreads();

  const int c128 = tid & 127;
  const int grp = tid >> 7;  // 0: pairs 0..5 (nodes 0-11), 1: pairs 6..10 (nodes 12-21)

  for (int t = 0; t < TT; t++) {
    const float* Yt = s->Y + t * NN;

    // ---- pass 1: layer1 Z & R  (C=256, input H1T) ----
    {
      int c = tid;
      float2 acc[11];
#pragma unroll
      for (int p = 0; p < 11; p++) acc[p] = make_float2(0.f, 0.f);
      dotcols<0, 11>(s->H1T, g_W1zr + c * 128, acc);
      int f = c & 127;
      bool isZ = (c < 128);
      float u = isZ ? s->uz[f] : s->ur[f];
      float cc = isZ ? s->cz[f] : s->cr[f];
#pragma unroll
      for (int p = 0; p < 11; p++) {
        int n0 = 2 * p;
        float v0 = sigmoidf_(acc[p].x + Yt[n0] * u + cc);
        if (isZ) s->ZT[f * NPAD + n0] = v0;
        else s->XT[f * NPAD + n0] = s->H1T[f * NPAD + n0] * v0;
        if (n0 + 1 < NN) {
          float v1 = sigmoidf_(acc[p].y + Yt[n0 + 1] * u + cc);
          if (isZ) s->ZT[f * NPAD + n0 + 1] = v1;
          else s->XT[f * NPAD + n0 + 1] = s->H1T[f * NPAD + n0 + 1] * v1;
        }
      }
    }
    __syncthreads();

    // ---- pass 2: layer1 h-gate + H1 update (C=128, input XT=H1*R) ----
    {
      int c = c128;
      const float* w = g_W1h + c * 128;
      float u = s->uh[c], cc = s->ch[c];
      if (grp == 0) {
        float2 acc[6];
#pragma unroll
        for (int p = 0; p < 6; p++) acc[p] = make_float2(0.f, 0.f);
        dotcols<0, 6>(s->XT, w, acc);
#pragma unroll
        for (int p = 0; p < 6; p++) {
          int n0 = 2 * p;
          {
            float ht = tanhf(acc[p].x + Yt[n0] * u + cc);
            float z = s->ZT[c * NPAD + n0], h = s->H1T[c * NPAD + n0];
            s->H1T[c * NPAD + n0] = z * h + (1.f - z) * ht;
          }
          {
            float ht = tanhf(acc[p].y + Yt[n0 + 1] * u + cc);
            float z = s->ZT[c * NPAD + n0 + 1], h = s->H1T[c * NPAD + n0 + 1];
            s->H1T[c * NPAD + n0 + 1] = z * h + (1.f - z) * ht;
          }
        }
      } else {
        float2 acc[5];
#pragma unroll
        for (int p = 0; p < 5; p++) acc[p] = make_float2(0.f, 0.f);
        dotcols<6, 5>(s->XT, w, acc);
#pragma unroll
        for (int p = 0; p < 5; p++) {
          int n0 = 2 * (6 + p);
          {
            float ht = tanhf(acc[p].x + Yt[n0] * u + cc);
            float z = s->ZT[c * NPAD + n0], h = s->H1T[c * NPAD + n0];
            s->H1T[c * NPAD + n0] = z * h + (1.f - z) * ht;
          }
          if (n0 + 1 < NN) {
            float ht = tanhf(acc[p].y + Yt[n0 + 1] * u + cc);
            float z = s->ZT[c * NPAD + n0 + 1], h = s->H1T[c * NPAD + n0 + 1];
            s->H1T[c * NPAD + n0 + 1] = z * h + (1.f - z) * ht;
          }
        }
      }
    }
    __syncthreads();

    // ---- pass 3: AH1 = A @ H1' (node mixing), store transposed into XT ----
    for (int idx = tid; idx < 128 * 11; idx += 256) {
      int k = idx / 11, p = idx - 11 * k;
      const float* hrow = s->H1T + k * NPAD;
      float2 acc2 = make_float2(0.f, 0.f);
#pragma unroll
      for (int j = 0; j < NN; j++) {
        float hv = hrow[j];
        float2 a2 = *reinterpret_cast<const float2*>(s->AT + j * NPAD + 2 * p);
        acc2 = ffma2(a2, make_float2(hv, hv), acc2);
      }
      *reinterpret_cast<float2*>(s->XT + k * NPAD + 2 * p) = acc2;
    }
    __syncthreads();

    // ---- pass 4: layer2 gcn pre-acts G2 = AH1 @ [Mz|Mr|Mh] (C=384) ----
    for (int c = tid; c < 384; c += 256) {
      float2 acc[11];
#pragma unroll
      for (int p = 0; p < 11; p++) acc[p] = make_float2(0.f, 0.f);
      dotcols<0, 11>(s->XT, g_W2g + c * 128, acc);
      int f = c & 127;
      float dterm = (c < 128) ? s->dz[f] : (c < 256) ? s->dr[f] : s->dh[f];
      float* dst = (c < 256) ? (s->GZR + c * NPAD) : (s->GH + (c - 256) * NPAD);
#pragma unroll
      for (int p = 0; p < 11; p++) {
        int n0 = 2 * p;
        dst[n0] = acc[p].x + dterm;
        if (n0 + 1 < NN) dst[n0 + 1] = acc[p].y + dterm;
      }
    }
    __syncthreads();

    // ---- pass 5: layer2 Z & R (C=256, input H2T) combined with GZR ----
    {
      int c = tid;
      float2 acc[11];
#pragma unroll
      for (int p = 0; p < 11; p++) acc[p] = make_float2(0.f, 0.f);
      dotcols<0, 11>(s->H2T, g_W2zr + c * 128, acc);
      int f = c & 127;
      bool isZ = (c < 128);
#pragma unroll
      for (int p = 0; p < 11; p++) {
        int n0 = 2 * p;
        {
          float v = sigmoidf_(acc[p].x + s->GZR[c * NPAD + n0]);
          if (isZ) s->ZT[f * NPAD + n0] = v;
          else s->XT[f * NPAD + n0] = s->H2T[f * NPAD + n0] * v;
        }
        if (n0 + 1 < NN) {
          float v = sigmoidf_(acc[p].y + s->GZR[c * NPAD + n0 + 1]);
          if (isZ) s->ZT[f * NPAD + n0 + 1] = v;
          else s->XT[f * NPAD + n0 + 1] = s->H2T[f * NPAD + n0 + 1] * v;
        }
      }
    }
    __syncthreads();

    // ---- pass 6: layer2 h-gate + H2 update + output accumulation ----
    {
      int c = c128;
      const float* w = g_W2h + c * 128;
      float osum = 0.f;
      if (grp == 0) {
        float2 acc[6];
#pragma unroll
        for (int p = 0; p < 6; p++) acc[p] = make_float2(0.f, 0.f);
        dotcols<0, 6>(s->XT, w, acc);
#pragma unroll
        for (int p = 0; p < 6; p++) {
          int n0 = 2 * p;
          {
            float ht = tanhf(acc[p].x + s->GH[c * NPAD + n0]);
            float z = s->ZT[c * NPAD + n0], h = s->H2T[c * NPAD + n0];
            float hn = z * h + (1.f - z) * ht;
            s->H2T[c * NPAD + n0] = hn;
            osum += hn;
          }
          {
            float ht = tanhf(acc[p].y + s->GH[c * NPAD + n0 + 1]);
            float z = s->ZT[c * NPAD + n0 + 1], h = s->H2T[c * NPAD + n0 + 1];
            float hn = z * h + (1.f - z) * ht;
            s->H2T[c * NPAD + n0 + 1] = hn;
            osum += hn;
          }
        }
      } else {
        float2 acc[5];
#pragma unroll
        for (int p = 0; p < 5; p++) acc[p] = make_float2(0.f, 0.f);
        dotcols<6, 5>(s->XT, w, acc);
#pragma unroll
        for (int p = 0; p < 5; p++) {
          int n0 = 2 * (6 + p);
          {
            float ht = tanhf(acc[p].x + s->GH[c * NPAD + n0]);
            float z = s->ZT[c * NPAD + n0], h = s->H2T[c * NPAD + n0];
            float hn = z * h + (1.f - z) * ht;
            s->H2T[c * NPAD + n0] = hn;
            osum += hn;
          }
          if (n0 + 1 < NN) {
            float ht = tanhf(acc[p].y + s->GH[c * NPAD + n0 + 1]);
            float z = s->ZT[c * NPAD + n0 + 1], h = s->H2T[c * NPAD + n0 + 1];
            float hn = z * h + (1.f - z) * ht;
            s->H2T[c * NPAD + n0 + 1] = hn;
            osum += hn;
          }
        }
      }
      s->OSUM[2 * c + grp] += osum;
    }
    __syncthreads();
  }

  // ---- final reduction: out[b] = (sum_c S[c]*clsw[c]) / (T*N) + clsb ----
  float v = 0.f;
  if (tid < 128) v = (s->OSUM[2 * tid] + s->OSUM[2 * tid + 1]) * s->clsw[tid];
#pragma unroll
  for (int off = 16; off > 0; off >>= 1) v += __shfl_down_sync(0xffffffffu, v, off);
  if ((tid & 31) == 0) s->red[tid >> 5] = v;
  __syncthreads();
  if (tid == 0) {
    float tot = 0.f;
#pragma unroll
    for (int wI = 0; wI < 8; wI++) tot += s->red[wI];
    out[b] = tot * (1.0f / (TT * NN)) + clsb[0];
  }
}

// ---------------- launch ----------------
extern "C" void kernel_launch(void* const* d_in, const int* in_sizes, int n_in,
                              void* d_out, int out_size) {
  const float* x = (const float*)d_in[0];
  const int* ei = (const int*)d_in[1];
  const float* ew = (const float*)d_in[2];
  const float* Wz1 = (const float*)d_in[3];
  const float* bz1 = (const float*)d_in[4];
  const float* lzw1 = (const float*)d_in[5];
  const float* lzb1 = (const float*)d_in[6];
  const float* Wr1 = (const float*)d_in[7];
  const float* br1 = (const float*)d_in[8];
  const float* lrw1 = (const float*)d_in[9];
  const float* lrb1 = (const float*)d_in[10];
  const float* Wh1 = (const float*)d_in[11];
  const float* bh1 = (const float*)d_in[12];
  const float* lhw1 = (const float*)d_in[13];
  const float* lhb1 = (const float*)d_in[14];
  const float* Wz2 = (const float*)d_in[15];
  const float* bz2 = (const float*)d_in[16];
  const float* lzw2 = (const float*)d_in[17];
  const float* lzb2 = (const float*)d_in[18];
  const float* Wr2 = (const float*)d_in[19];
  const float* br2 = (const float*)d_in[20];
  const float* lrw2 = (const float*)d_in[21];
  const float* lrb2 = (const float*)d_in[22];
  const float* Wh2 = (const float*)d_in[23];
  const float* bh2 = (const float*)d_in[24];
  const float* lhw2 = (const float*)d_in[25];
  const float* lhb2 = (const float*)d_in[26];
  const float* clsw = (const float*)d_in[27];
  const float* clsb = (const float*)d_in[28];
  int E = in_sizes[1] / 2;

  prep_A_kernel<<<1, 32>>>(ei, ew, E);
  prep_W_kernel<<<128, 256>>>(Wz1, bz1, lzw1, lzb1, Wr1, br1, lrw1, lrb1, Wh1,
                              bh1, lhw1, lhb1, Wz2, bz2, lzw2, lzb2, Wr2, br2,
                              lrw2, lrb2, Wh2, bh2, lhw2, lhb2);

  cudaFuncSetAttribute(tgcn_main, cudaFuncAttributeMaxDynamicSharedMemorySize,
                       (int)sizeof(SM));
  tgcn_main<<<BB, 256, sizeof(SM)>>>(x, clsw, clsb, (float*)d_out);
}